// round 16
// baseline (speedup 1.0000x reference)
#include <cuda_runtime.h>
#include <cuda_fp16.h>
#include <math.h>

// Problem constants
#define BATCH    4
#define NTOK     2304      // 48*48
#define GRID_H   48
#define GRID_W   48
#define EMBED    128
#define HEADS    8
#define HDIM     16
#define RY       3         // KH//2
#define RX       5         // KW//2

#define QSCALE   0.08838834764831845f   // 128^-0.5

__device__ float g_qkv[3u * BATCH * HEADS * NTOK * HDIM];   // ~14.2 MB
__device__ float g_att[(size_t)BATCH * NTOK * EMBED];       // ~4.7 MB

typedef unsigned int u32;
typedef unsigned long long u64;

// tf32 helpers (GEMM kernels).
__device__ __forceinline__ u32 f2tf(float f) {
    u32 u; asm("cvt.rna.tf32.f32 %0, %1;" : "=r"(u) : "f"(f)); return u;
}
#define MMA_TF32(c0,c1,c2,c3, a0,a1,a2,a3, b0,b1) \
    asm("mma.sync.aligned.m16n8k8.row.col.f32.tf32.tf32.f32 " \
        "{%0,%1,%2,%3}, {%4,%5,%6,%7}, {%8,%9}, {%0,%1,%2,%3};" \
        : "+f"(c0), "+f"(c1), "+f"(c2), "+f"(c3) \
        : "r"(a0), "r"(a1), "r"(a2), "r"(a3), "r"(b0), "r"(b1))

#define ASTR 136   // 128+8: frag-load banks g+8t -> conflict-free
#define WSTR 72    // 64+8

// ---------------------------------------------------------------------------
// Shared tf32 MMA mainloop: C[128x64] += A[128xK] * W[64xK]^T, K=128, BK=32
// (8 syncs/block instead of 16; 4 k8 steps per stage).
// 256 threads = 8 warps in 4(m) x 2(n); warp tile 32x32 = 2x4 m16n8k8 tiles.
// ---------------------------------------------------------------------------
__device__ __forceinline__ void mma_mainloop(
    const float* __restrict__ pa, const float* __restrict__ pw,
    u32 As[32][ASTR], u32 Ws[32][WSTR],
    float c[2][4][4], int tid)
{
    const int arow = tid >> 1, acol = (tid & 1) * 16;   // A: 4 f4/thread
    const int wrow = tid >> 2, wcol = (tid & 3) * 8;    // W: 2 f4/thread
    const int lane = tid & 31, wid = tid >> 5;
    const int g = lane >> 2, t = lane & 3;
    const int mw = (wid >> 1) * 32, nw = (wid & 1) * 32;

    float4 ra[4], rw[2];
    #pragma unroll
    for (int i = 0; i < 4; i++) ra[i] = *(const float4*)(pa + 4 * i);
    #pragma unroll
    for (int i = 0; i < 2; i++) rw[i] = *(const float4*)(pw + 4 * i);

    for (int k0 = 0; k0 < EMBED; k0 += 32) {
        #pragma unroll
        for (int i = 0; i < 4; i++) {
            As[acol + 4 * i + 0][arow] = f2tf(ra[i].x);
            As[acol + 4 * i + 1][arow] = f2tf(ra[i].y);
            As[acol + 4 * i + 2][arow] = f2tf(ra[i].z);
            As[acol + 4 * i + 3][arow] = f2tf(ra[i].w);
        }
        #pragma unroll
        for (int i = 0; i < 2; i++) {
            Ws[wcol + 4 * i + 0][wrow] = f2tf(rw[i].x);
            Ws[wcol + 4 * i + 1][wrow] = f2tf(rw[i].y);
            Ws[wcol + 4 * i + 2][wrow] = f2tf(rw[i].z);
            Ws[wcol + 4 * i + 3][wrow] = f2tf(rw[i].w);
        }
        __syncthreads();
        if (k0 + 32 < EMBED) {
            #pragma unroll
            for (int i = 0; i < 4; i++)
                ra[i] = *(const float4*)(pa + k0 + 32 + 4 * i);
            #pragma unroll
            for (int i = 0; i < 2; i++)
                rw[i] = *(const float4*)(pw + k0 + 32 + 4 * i);
        }
        #pragma unroll
        for (int kk = 0; kk < 32; kk += 8) {
            u32 b[4][2];
            #pragma unroll
            for (int j = 0; j < 4; j++) {
                b[j][0] = Ws[kk + t][nw + 8 * j + g];
                b[j][1] = Ws[kk + t + 4][nw + 8 * j + g];
            }
            #pragma unroll
            for (int i = 0; i < 2; i++) {
                u32 a0 = As[kk + t][mw + 16 * i + g];
                u32 a1 = As[kk + t][mw + 16 * i + g + 8];
                u32 a2 = As[kk + t + 4][mw + 16 * i + g];
                u32 a3 = As[kk + t + 4][mw + 16 * i + g + 8];
                #pragma unroll
                for (int j = 0; j < 4; j++)
                    MMA_TF32(c[i][j][0], c[i][j][1], c[i][j][2], c[i][j][3],
                             a0, a1, a2, a3, b[j][0], b[j][1]);
            }
        }
        __syncthreads();
    }
}

// ---------------------------------------------------------------------------
// QKV GEMM (tf32 mma): scatter into g_qkv [which][b][head][t][d], q scaled.
// ---------------------------------------------------------------------------
__global__ __launch_bounds__(256)
void qkv_gemm_kernel(const float* __restrict__ A, const float* __restrict__ W,
                     const float* __restrict__ bias)
{
    __shared__ u32 As[32][ASTR];
    __shared__ u32 Ws[32][WSTR];
    const int tid = threadIdx.x;
    const int m0 = blockIdx.y * 128, n0 = blockIdx.x * 64;

    const float* pa = &A[(size_t)(m0 + (tid >> 1)) * EMBED + (tid & 1) * 16];
    const float* pw = &W[(size_t)(n0 + (tid >> 2)) * EMBED + (tid & 3) * 8];

    float c[2][4][4] = {};
    mma_mainloop(pa, pw, As, Ws, c, tid);

    const int lane = tid & 31, wid = tid >> 5;
    const int g = lane >> 2, t = lane & 3;
    const int mw = (wid >> 1) * 32, nw = (wid & 1) * 32;

    const int which = n0 >> 7;
    const float sc = (which == 0) ? QSCALE : 1.0f;
    const size_t wbase = (size_t)which * BATCH * HEADS * NTOK * HDIM;

    #pragma unroll
    for (int j = 0; j < 4; j++) {
        const int nn = nw + 8 * j + 2 * t;
        const int n  = n0 + nn;
        const int head = (n & 127) >> 4;
        const int d    = nn & 15;
        const float b0v = bias[n], b1v = bias[n + 1];
        #pragma unroll
        for (int i = 0; i < 2; i++) {
            #pragma unroll
            for (int half = 0; half < 2; half++) {
                int r = m0 + mw + 16 * i + g + half * 8;
                int b = r / NTOK;
                int tok = r - b * NTOK;
                size_t idx = wbase
                    + ((size_t)b * HEADS + head) * (NTOK * HDIM)
                    + (size_t)tok * HDIM + d;
                float2 v;
                v.x = (c[i][j][half * 2 + 0] + b0v) * sc;
                v.y = (c[i][j][half * 2 + 1] + b1v) * sc;
                *(float2*)&g_qkv[idx] = v;
            }
        }
    }
}

// ---------------------------------------------------------------------------
// Proj GEMM (tf32 mma): A = g_att, W = proj_w -> d_out.
// ---------------------------------------------------------------------------
__global__ __launch_bounds__(256)
void proj_gemm_kernel(const float* __restrict__ W, const float* __restrict__ bias,
                      float* __restrict__ out)
{
    __shared__ u32 As[32][ASTR];
    __shared__ u32 Ws[32][WSTR];
    const int tid = threadIdx.x;
    const int m0 = blockIdx.y * 128, n0 = blockIdx.x * 64;

    const float* pa = &g_att[(size_t)(m0 + (tid >> 1)) * EMBED + (tid & 1) * 16];
    const float* pw = &W[(size_t)(n0 + (tid >> 2)) * EMBED + (tid & 3) * 8];

    float c[2][4][4] = {};
    mma_mainloop(pa, pw, As, Ws, c, tid);

    const int lane = tid & 31, wid = tid >> 5;
    const int g = lane >> 2, t = lane & 3;
    const int mw = (wid >> 1) * 32, nw = (wid & 1) * 32;

    #pragma unroll
    for (int j = 0; j < 4; j++) {
        const int n = n0 + nw + 8 * j + 2 * t;
        const float b0v = bias[n], b1v = bias[n + 1];
        #pragma unroll
        for (int i = 0; i < 2; i++) {
            #pragma unroll
            for (int half = 0; half < 2; half++) {
                int r = m0 + mw + 16 * i + g + half * 8;
                float2 v;
                v.x = c[i][j][half * 2 + 0] + b0v;
                v.y = c[i][j][half * 2 + 1] + b1v;
                *(float2*)&out[(size_t)r * EMBED + n] = v;
            }
        }
    }
}

// ---------------------------------------------------------------------------
// Windowed attention: block = (2 rows, head, batch), 96 threads, one query
// per thread. K AND V in fp16 smem (12+12 = 24 KB): halves the smem-crossbar
// bytes (the measured bound). Scores: cvt half2->float2 + fp32 fmaf (two
// chains); q stays fp32. Output fp32. Token-major: conflict-free LDS.128.
// ---------------------------------------------------------------------------
#define SROW 384   // 8 rows x 48 tokens

__global__ __launch_bounds__(96)
void win_attn_kernel()
{
    __shared__ uint4 sKh[2][SROW];   // 12288 B (fp16 K)
    __shared__ uint4 sVh[2][SROW];   // 12288 B (fp16 V)

    const int h0   = blockIdx.x * 2;
    const int head = blockIdx.y;
    const int b    = blockIdx.z;
    const int tid  = threadIdx.x;     // 0..95

    const int r0 = max(h0 - RY, 0);
    const int r1 = min(h0 + 1 + RY, GRID_H - 1);
    const int nr = r1 - r0 + 1;          // <= 8

    const size_t base  = ((size_t)b * HEADS + head) * (NTOK * HDIM);
    const size_t plane = (size_t)BATCH * HEADS * NTOK * HDIM;
    const float* gq = g_qkv + base;
    const float* gk = g_qkv + plane + base;
    const float* gv = g_qkv + 2 * plane + base;

    // Stage K and V rows [r0..r1] as fp16, token-major.
    {
        const int nt = nr * GRID_W;
        const float4* srcK = (const float4*)(gk + (size_t)r0 * GRID_W * HDIM);
        const float4* srcV = (const float4*)(gv + (size_t)r0 * GRID_W * HDIM);
        for (int t = tid; t < nt; t += 96) {
            #pragma unroll
            for (int s = 0; s < 2; s++) {
                const float4* src = s ? srcV : srcK;
                float4 v0 = src[t * 4 + 0], v1 = src[t * 4 + 1];
                float4 v2 = src[t * 4 + 2], v3 = src[t * 4 + 3];
                __half2 h0p = __floats2half2_rn(v0.x, v0.y);
                __half2 h1p = __floats2half2_rn(v0.z, v0.w);
                __half2 h2p = __floats2half2_rn(v1.x, v1.y);
                __half2 h3p = __floats2half2_rn(v1.z, v1.w);
                __half2 h4p = __floats2half2_rn(v2.x, v2.y);
                __half2 h5p = __floats2half2_rn(v2.z, v2.w);
                __half2 h6p = __floats2half2_rn(v3.x, v3.y);
                __half2 h7p = __floats2half2_rn(v3.z, v3.w);
                uint4 pa, pb;
                pa.x = *(u32*)&h0p; pa.y = *(u32*)&h1p;
                pa.z = *(u32*)&h2p; pa.w = *(u32*)&h3p;
                pb.x = *(u32*)&h4p; pb.y = *(u32*)&h5p;
                pb.z = *(u32*)&h6p; pb.w = *(u32*)&h7p;
                if (s) { sVh[0][t] = pa; sVh[1][t] = pb; }
                else   { sKh[0][t] = pa; sKh[1][t] = pb; }
            }
        }
    }
    __syncthreads();

    const int qr = (tid >= GRID_W) ? 1 : 0;
    const int w  = tid - qr * GRID_W;
    const int h  = h0 + qr;

    float qf[16];
    {
        const float4* qp = (const float4*)(gq + ((size_t)h * GRID_W + w) * HDIM);
        #pragma unroll
        for (int j = 0; j < 4; j++) {
            float4 v = qp[j];
            qf[4*j+0] = v.x; qf[4*j+1] = v.y; qf[4*j+2] = v.z; qf[4*j+3] = v.w;
        }
    }

    float den = 0.f;
    float acc[16] = {};

    #pragma unroll
    for (int dy = -RY; dy <= RY; dy++) {
        const int hh = h + dy;
        if ((unsigned)hh >= GRID_H) continue;
        const int rb = (hh - r0) * GRID_W;
        #pragma unroll
        for (int dx = -RX; dx <= RX; dx++) {
            const int wc = w + dx;
            if ((unsigned)wc >= GRID_W) continue;
            const int slot = rb + wc;

            uint4 ka = sKh[0][slot];
            uint4 kb = sKh[1][slot];
            float s0 = 0.f, s1 = 0.f;
            float2 f;
            f = __half22float2(*(__half2*)&ka.x);
            s0 = fmaf(qf[0],  f.x, s0); s1 = fmaf(qf[1],  f.y, s1);
            f = __half22float2(*(__half2*)&ka.y);
            s0 = fmaf(qf[2],  f.x, s0); s1 = fmaf(qf[3],  f.y, s1);
            f = __half22float2(*(__half2*)&ka.z);
            s0 = fmaf(qf[4],  f.x, s0); s1 = fmaf(qf[5],  f.y, s1);
            f = __half22float2(*(__half2*)&ka.w);
            s0 = fmaf(qf[6],  f.x, s0); s1 = fmaf(qf[7],  f.y, s1);
            f = __half22float2(*(__half2*)&kb.x);
            s0 = fmaf(qf[8],  f.x, s0); s1 = fmaf(qf[9],  f.y, s1);
            f = __half22float2(*(__half2*)&kb.y);
            s0 = fmaf(qf[10], f.x, s0); s1 = fmaf(qf[11], f.y, s1);
            f = __half22float2(*(__half2*)&kb.z);
            s0 = fmaf(qf[12], f.x, s0); s1 = fmaf(qf[13], f.y, s1);
            f = __half22float2(*(__half2*)&kb.w);
            s0 = fmaf(qf[14], f.x, s0); s1 = fmaf(qf[15], f.y, s1);

            float e = __expf(s0 + s1);
            den += e;

            uint4 va = sVh[0][slot];
            uint4 vb = sVh[1][slot];
            f = __half22float2(*(__half2*)&va.x);
            acc[0]  = fmaf(e, f.x, acc[0]);  acc[1]  = fmaf(e, f.y, acc[1]);
            f = __half22float2(*(__half2*)&va.y);
            acc[2]  = fmaf(e, f.x, acc[2]);  acc[3]  = fmaf(e, f.y, acc[3]);
            f = __half22float2(*(__half2*)&va.z);
            acc[4]  = fmaf(e, f.x, acc[4]);  acc[5]  = fmaf(e, f.y, acc[5]);
            f = __half22float2(*(__half2*)&va.w);
            acc[6]  = fmaf(e, f.x, acc[6]);  acc[7]  = fmaf(e, f.y, acc[7]);
            f = __half22float2(*(__half2*)&vb.x);
            acc[8]  = fmaf(e, f.x, acc[8]);  acc[9]  = fmaf(e, f.y, acc[9]);
            f = __half22float2(*(__half2*)&vb.y);
            acc[10] = fmaf(e, f.x, acc[10]); acc[11] = fmaf(e, f.y, acc[11]);
            f = __half22float2(*(__half2*)&vb.z);
            acc[12] = fmaf(e, f.x, acc[12]); acc[13] = fmaf(e, f.y, acc[13]);
            f = __half22float2(*(__half2*)&vb.w);
            acc[14] = fmaf(e, f.x, acc[14]); acc[15] = fmaf(e, f.y, acc[15]);
        }
    }

    const float inv = 1.f / den;
    float* op = g_att + ((size_t)b * NTOK + h * GRID_W + w) * EMBED
              + head * HDIM;
    #pragma unroll
    for (int j = 0; j < 4; j++) {
        *(float4*)&op[j * 4] = make_float4(acc[4*j+0] * inv, acc[4*j+1] * inv,
                                           acc[4*j+2] * inv, acc[4*j+3] * inv);
    }
}

// ---------------------------------------------------------------------------
extern "C" void kernel_launch(void* const* d_in, const int* in_sizes, int n_in,
                              void* d_out, int out_size)
{
    const float* x      = (const float*)d_in[0];  // [4, 2304, 128]
    const float* qkv_w  = (const float*)d_in[1];  // [384, 128]
    const float* qkv_b  = (const float*)d_in[2];  // [384]
    const float* proj_w = (const float*)d_in[3];  // [128, 128]
    const float* proj_b = (const float*)d_in[4];  // [128]
    // d_in[5] (mask) unused: window computed structurally.
    float* out = (float*)d_out;                   // [4, 2304, 128]

    const int M = BATCH * NTOK;  // 9216

    dim3 g1(6, M / 128);                 // 6 x 72 = 432
    qkv_gemm_kernel<<<g1, 256>>>(x, qkv_w, qkv_b);

    dim3 g2(GRID_H / 2, HEADS, BATCH);   // 24 x 8 x 4 = 768
    win_attn_kernel<<<g2, 96>>>();

    dim3 g3(EMBED / 64, M / 128);        // 2 x 72 = 144
    proj_gemm_kernel<<<g3, 256>>>(proj_w, proj_b, out);
}